// round 13
// baseline (speedup 1.0000x reference)
#include <cuda_runtime.h>
#include <cuda_bf16.h>

#define BB 16
#define FF 32
#define CC 32
#define NN 200
#define TT 48
#define SS 3
#define MC 16               // m-chunk in agg (2 k-steps of 8)
#define NCH 13              // 12 full chunks + 1 partial (8)
#define NP 224              // padded N (14 x 16-row mma bands)
#define WS 20               // wsm row stride (conflict-free: 20 % 8 == 4)
#define NTFLAT (NN * TT)    // 9600

// ---- tf32 helpers ----
__device__ __forceinline__ unsigned tf32r(float f) {
    unsigned u; asm("cvt.rna.tf32.f32 %0, %1;" : "=r"(u) : "f"(f)); return u;
}
__device__ __forceinline__ void mma_tf32(float* d,
    unsigned a0, unsigned a1, unsigned a2, unsigned a3,
    unsigned b0, unsigned b1)
{
    asm("mma.sync.aligned.m16n8k8.row.col.f32.tf32.tf32.f32 "
        "{%0,%1,%2,%3}, {%4,%5,%6,%7}, {%8,%9}, {%0,%1,%2,%3};"
        : "+f"(d[0]), "+f"(d[1]), "+f"(d[2]), "+f"(d[3])
        : "r"(a0), "r"(a1), "r"(a2), "r"(a3), "r"(b0), "r"(b1));
}

// ---- cp.async helpers ----
__device__ __forceinline__ unsigned smem_u32(const void* p) {
    return (unsigned)__cvta_generic_to_shared(p);
}
#define CPA16(d, s) asm volatile("cp.async.cg.shared.global [%0], [%1], 16;" :: "r"(d), "l"(s))
#define CPC()       asm volatile("cp.async.commit_group;")
#define CPW0()      asm volatile("cp.async.wait_group 0;" ::: "memory")

// Scratch (device globals)
__device__ float g_wh[SS][BB][NTFLAT * CC];       // tf32-rounded Wh, [(n,t)][c]
__device__ float g_f1t[SS][BB][TT * NP];          // [t][n]
__device__ float g_f2t[SS][BB][TT * NP];          // [t][n]
__device__ unsigned g_adjb[BB * SS][NCH][NP];     // 16-bit masks per chunk
__device__ float g_y[6][BB][NTFLAT * CC];         // slot = 2*s + hop

// ---------------------------------------------------------------------------
// Adjacency bit-pack (16 bits per chunk word). grid 48, 256 threads.
// ---------------------------------------------------------------------------
__global__ void adjbit_kernel(const int* __restrict__ support)
{
    const int bs = blockIdx.x;
    const int warp = threadIdx.x >> 5, lane = threadIdx.x & 31;
    const int* adj = support + (size_t)bs * NN * NN;
    for (int pid = warp; pid < NN * NCH; pid += 8) {
        int n = pid / NCH, wi = pid % NCH;
        int mm = wi * MC + lane;
        int v = (lane < MC && mm < NN) ? (adj[n * NN + mm] > 0) : 0;
        unsigned word = __ballot_sync(0xffffffffu, v);
        if (lane == 0) g_adjb[bs][wi][n] = word;
    }
    if (threadIdx.x < NP - NN) {
        for (int wi = 0; wi < NCH; wi++) g_adjb[bs][wi][NN + threadIdx.x] = 0u;
    }
}

// ---------------------------------------------------------------------------
// Wh + f1/f2 (t-major f-outputs; Wh stored pre-rounded to tf32).
// grid (75, BB, SS), 256 threads.
// ---------------------------------------------------------------------------
__global__ __launch_bounds__(256) void wh_kernel(
    const float* __restrict__ xin,
    const float* __restrict__ Wb,
    const float* __restrict__ ab,
    int layout)
{
    const int b = blockIdx.y, s = blockIdx.z;
    const int base = blockIdx.x * 128;
    const int tid = threadIdx.x;

    __shared__ float xs[128 * 33];
    __shared__ float Ws[FF * CC];
    __shared__ float as_[2 * CC];

    if (layout == 0) {
        const float* src = xin + (size_t)b * FF * NTFLAT + base;
        #pragma unroll
        for (int k = 0; k < 4; k++) {
            int idx4 = tid + 256 * k;
            int f = idx4 >> 5, r4 = (idx4 & 31) * 4;
            float4 v = *(const float4*)(src + (size_t)f * NTFLAT + r4);
            xs[(r4 + 0) * 33 + f] = v.x;
            xs[(r4 + 1) * 33 + f] = v.y;
            xs[(r4 + 2) * 33 + f] = v.z;
            xs[(r4 + 3) * 33 + f] = v.w;
        }
    } else {
        const float* src = &g_y[2 * s][b][(size_t)base * CC];
        #pragma unroll
        for (int k = 0; k < 4; k++) {
            int idx4 = tid + 256 * k;
            int row = idx4 >> 3, q = (idx4 & 7) * 4;
            float4 v = *(const float4*)(src + idx4 * 4);
            xs[row * 33 + q + 0] = v.x;
            xs[row * 33 + q + 1] = v.y;
            xs[row * 33 + q + 2] = v.z;
            xs[row * 33 + q + 3] = v.w;
        }
    }
    {
        const float* W = Wb + (s * BB + b) * (FF * CC);
        if (tid < 256) ((float4*)Ws)[tid] = ((const float4*)W)[tid];
        if (tid < 2 * CC) as_[tid] = ab[(s * BB + b) * (2 * CC) + tid];
    }
    __syncthreads();

    const int cg = tid & 15, rg = tid >> 4;
    const int r0 = rg * 8;
    float acc[8][2];
    #pragma unroll
    for (int i = 0; i < 8; i++) { acc[i][0] = 0.f; acc[i][1] = 0.f; }

    #pragma unroll 8
    for (int f = 0; f < FF; f++) {
        float2 wv = *(const float2*)&Ws[f * CC + 2 * cg];
        #pragma unroll
        for (int i = 0; i < 8; i++) {
            float xv = xs[(r0 + i) * 33 + f];
            acc[i][0] += xv * wv.x;
            acc[i][1] += xv * wv.y;
        }
    }

    float* hp = &g_wh[s][b][0];
    #pragma unroll
    for (int i = 0; i < 8; i++) {
        unsigned h0 = tf32r(acc[i][0]);
        unsigned h1 = tf32r(acc[i][1]);
        size_t off = (size_t)(base + r0 + i) * CC + 2 * cg;
        *(float2*)&hp[off] = make_float2(__uint_as_float(h0), __uint_as_float(h1));
    }

    float a1l = as_[2 * cg], a1h = as_[2 * cg + 1];
    float a2l = as_[CC + 2 * cg], a2h = as_[CC + 2 * cg + 1];
    #pragma unroll
    for (int i = 0; i < 8; i++) {
        float p1 = acc[i][0] * a1l + acc[i][1] * a1h;
        float p2 = acc[i][0] * a2l + acc[i][1] * a2h;
        #pragma unroll
        for (int off = 8; off >= 1; off >>= 1) {
            p1 += __shfl_xor_sync(0xffffffffu, p1, off);
            p2 += __shfl_xor_sync(0xffffffffu, p2, off);
        }
        if (cg == 0) {
            int row = base + r0 + i;
            int n = row / TT, t = row % TT;
            g_f1t[s][b][t * NP + n] = p1;
            g_f2t[s][b][t * NP + n] = p2;
        }
    }
}

// ---------------------------------------------------------------------------
// Attention-aggregation, 1x tf32 mma, fused single-barrier pipeline.
// f2max computed in-CTA; weights stored pre-rounded to tf32 by step1.
// grid (TT, BB, SS), block 448 (14 warps). Warp w owns n-rows [16w, 16w+16).
// ---------------------------------------------------------------------------
__global__ __launch_bounds__(448, 2) void agg_kernel(int hop)
{
    const int t = blockIdx.x, b = blockIdx.y, s = blockIdx.z;
    const int bs = b * SS + s;
    const int tid = threadIdx.x;
    const int lane = tid & 31, wid = tid >> 5;
    const int grp = lane >> 2, kq = lane & 3;

    __shared__ __align__(16) float whs[2][MC * 36];      // [m][c] stride 36
    __shared__ __align__(16) float wsm[2][NP * WS];      // [n][m] stride 20
    __shared__ __align__(16) unsigned adjw[2][NP];
    __shared__ float f2all[NP];
    __shared__ float zsm[NP];

    const float* whbase = &g_wh[s][b][0];
    const float* f1tp = &g_f1t[s][b][t * NP];
    const float* f2tp = &g_f2t[s][b][t * NP];

    auto prefetch_whs = [&](int k) {
        const int bf = k & 1;
        if (tid < MC * 8) {                 // 128 threads
            int m = tid >> 3, q = tid & 7;
            int mrow = min(k * MC + m, NN - 1);
            CPA16(smem_u32(&whs[bf][m * 36 + q * 4]),
                  whbase + ((size_t)mrow * TT + t) * CC + q * 4);
        }
    };
    auto prefetch_adj = [&](int k) {
        const int bf = k & 1;
        if (tid < NP / 4)
            CPA16(smem_u32(&adjw[bf][tid * 4]), &g_adjb[bs][k][tid * 4]);
    };

    float f1v = 0.f, mhv = 0.f, z = 0.f;

    // step1 for chunk kk (threads < NN): tf32-rounded weights -> wsm[kk&1]
    auto step1 = [&](int kk) {
        if (tid < NN) {
            const int bf = kk & 1;
            unsigned aw = adjw[bf][tid];
            const int mcn = (kk == NCH - 1) ? (NN - (NCH - 1) * MC) : MC;
            const int mb = kk * MC;
            #pragma unroll
            for (int q = 0; q < MC / 4; q++) {
                if (4 * q >= mcn) break;
                float4 wq;
                float* wp = &wq.x;
                #pragma unroll
                for (int j = 0; j < 4; j++) {
                    int m = 4 * q + j;
                    float sv = f1v + f2all[mb + m];
                    float e = fmaxf(sv, 0.2f * sv);
                    float w = ((aw >> m) & 1u) ? __expf(e - mhv) : 0.f;
                    float wr = __uint_as_float(tf32r(w));
                    wp[j] = wr;
                    z += wr;
                }
                *(float4*)&wsm[bf][tid * WS + 4 * q] = wq;
            }
        }
    };

    // ---- prologue ----
    prefetch_whs(0);
    prefetch_adj(0);
    prefetch_adj(1);
    CPC();

    // f2 row into smem (pad = -inf for the max)
    if (tid < NP) f2all[tid] = (tid < NN) ? f2tp[tid] : -1e30f;
    // zero wsm pad rows [NN, NP) in both buffers
    for (int i = tid; i < (NP - NN) * WS; i += 448) {
        int n = NN + i / WS, m = i % WS;
        wsm[0][n * WS + m] = 0.f;
        wsm[1][n * WS + m] = 0.f;
    }

    CPW0();
    __syncthreads();       // f2all + chunk0/1 adj + whs(0) visible

    // every warp redundantly reduces f2all -> fms (no extra barrier)
    float fms;
    {
        float m = -1e30f;
        #pragma unroll
        for (int i = 0; i < 7; i++) m = fmaxf(m, f2all[lane + 32 * i]);
        #pragma unroll
        for (int off = 16; off >= 1; off >>= 1)
            m = fmaxf(m, __shfl_xor_sync(0xffffffffu, m, off));
        fms = m;
    }
    if (tid < NN) {
        f1v = f1tp[tid];
        float sv = f1v + fms;
        mhv = fmaxf(sv, 0.2f * sv);
    }

    step1(0);
    __syncthreads();       // publish wsm(0)

    float d[4][4];
    #pragma unroll
    for (int j = 0; j < 4; j++)
        #pragma unroll
        for (int q = 0; q < 4; q++) d[j][q] = 0.f;

    const int r0 = 16 * wid + grp;

    for (int k = 0; k < NCH; k++) {
        const int bf = k & 1;
        if (k + 1 < NCH) prefetch_whs(k + 1);
        if (k + 2 < NCH) prefetch_adj(k + 2);
        CPC();

        if (k + 1 < NCH) step1(k + 1);

        // step2 for k: tf32 mma from wsm[bf] (pre-rounded), whs[bf]
        const int mc = (k == NCH - 1) ? (NN - (NCH - 1) * MC) : MC;
        const int nks = mc >> 3;
        for (int ks = 0; ks < nks; ks++) {
            unsigned a0 = __float_as_uint(wsm[bf][r0 * WS + ks * 8 + kq]);
            unsigned a1 = __float_as_uint(wsm[bf][(r0 + 8) * WS + ks * 8 + kq]);
            unsigned a2 = __float_as_uint(wsm[bf][r0 * WS + ks * 8 + kq + 4]);
            unsigned a3 = __float_as_uint(wsm[bf][(r0 + 8) * WS + ks * 8 + kq + 4]);
            #pragma unroll
            for (int j = 0; j < 4; j++) {
                int c0 = 8 * j + grp;
                int mr = ks * 8 + kq;
                unsigned bh0 = __float_as_uint(whs[bf][mr * 36 + c0]);
                unsigned bh1 = __float_as_uint(whs[bf][(mr + 4) * 36 + c0]);
                mma_tf32(d[j], a0, a1, a2, a3, bh0, bh1);
            }
        }

        CPW0();
        __syncthreads();   // publish wsm(k+1); free whs[bf]/wsm[bf]
    }

    if (tid < NN) zsm[tid] = z;
    __syncthreads();

    const int slot = 2 * s + hop;
    float* yp = &g_y[slot][b][0];
    #pragma unroll
    for (int half = 0; half < 2; half++) {
        int n = r0 + 8 * half;
        if (n < NN) {
            float zv = fmaxf(zsm[n], 1e-30f);
            #pragma unroll
            for (int j = 0; j < 4; j++) {
                float h0 = __fdividef(d[j][2 * half], zv);
                float h1 = __fdividef(d[j][2 * half + 1], zv);
                float y0, y1;
                if (hop == 0) {
                    y0 = (h0 > 0.f) ? h0 : (__expf(h0) - 1.f);
                    y1 = (h1 > 0.f) ? h1 : (__expf(h1) - 1.f);
                } else {
                    y0 = fmaxf(h0, 0.f);
                    y1 = fmaxf(h1, 0.f);
                }
                *(float2*)&yp[(size_t)(n * TT + t) * CC + 8 * j + 2 * kq] =
                    make_float2(y0, y1);
            }
        }
    }
}

// ---------------------------------------------------------------------------
// Final concat + 1x1 conv, cp.async double-buffered. grid (NN, BB), block 192.
// ---------------------------------------------------------------------------
__global__ __launch_bounds__(192) void mlp_kernel(
    const float* __restrict__ x,
    const float* __restrict__ mw,
    const float* __restrict__ mb,
    float* __restrict__ out)
{
    const int n = blockIdx.x, b = blockIdx.y;
    const int tid = threadIdx.x;
    __shared__ __align__(16) float hb[2][TT * 32];
    __shared__ __align__(16) float wb[2][64 * 36];

    auto prefetch = [&](int blk, int bf) {
        const float* src = &g_y[blk - 1][b][(size_t)n * TT * CC];
        #pragma unroll
        for (int i = tid; i < 384; i += 192)
            CPA16(smem_u32(&hb[bf][i * 4]), src + i * 4);
        #pragma unroll
        for (int i = tid; i < 512; i += 192) {
            int o = i >> 3, q = i & 7;
            CPA16(smem_u32(&wb[bf][o * 36 + q * 4]), mw + o * 224 + blk * 32 + q * 4);
        }
        CPC();
    };

    for (int idx = tid; idx < TT * 32; idx += 192) {
        int f = idx / TT, t = idx % TT;
        hb[0][t * 32 + f] = x[((size_t)(b * FF + f) * NN + n) * TT + t];
    }
    for (int idx = tid; idx < 64 * 32; idx += 192) {
        int o = idx / 32, c = idx % 32;
        wb[0][o * 36 + c] = mw[o * 224 + c];
    }
    prefetch(1, 1);
    __syncthreads();

    const int og = tid % 16, tg = tid / 16;
    float acc[4][4];
    #pragma unroll
    for (int i = 0; i < 4; i++)
        #pragma unroll
        for (int j = 0; j < 4; j++) acc[i][j] = 0.f;

    for (int blk = 0; blk < 7; blk++) {
        const int bf = blk & 1;
        #pragma unroll
        for (int cc = 0; cc < 32; cc += 4) {
            float4 hv[4], wv[4];
            #pragma unroll
            for (int j = 0; j < 4; j++) hv[j] = *(const float4*)&hb[bf][(tg * 4 + j) * 32 + cc];
            #pragma unroll
            for (int i = 0; i < 4; i++) wv[i] = *(const float4*)&wb[bf][(og + 16 * i) * 36 + cc];
            #pragma unroll
            for (int i = 0; i < 4; i++)
                #pragma unroll
                for (int j = 0; j < 4; j++)
                    acc[i][j] += wv[i].x * hv[j].x + wv[i].y * hv[j].y
                               + wv[i].z * hv[j].z + wv[i].w * hv[j].w;
        }
        if (blk + 1 < 7) {
            CPW0();
            __syncthreads();
            if (blk + 2 < 7) prefetch(blk + 2, bf);
        }
    }

    #pragma unroll
    for (int i = 0; i < 4; i++) {
        int o = og + 16 * i;
        float bias = mb[o];
        float4 r = make_float4(acc[i][0] + bias, acc[i][1] + bias,
                               acc[i][2] + bias, acc[i][3] + bias);
        *(float4*)&out[((size_t)(b * 64 + o) * NN + n) * TT + tg * 4] = r;
    }
}

// ---------------------------------------------------------------------------
extern "C" void kernel_launch(void* const* d_in, const int* in_sizes, int n_in,
                              void* d_out, int out_size)
{
    const float* x       = (const float*)d_in[0];
    const int*   support = (const int*)  d_in[1];
    const float* W1      = (const float*)d_in[2];
    const float* a1      = (const float*)d_in[3];
    const float* WK      = (const float*)d_in[4];
    const float* aK      = (const float*)d_in[5];
    const float* mw      = (const float*)d_in[6];
    const float* mb      = (const float*)d_in[7];
    float* out = (float*)d_out;

    dim3 gwh(NTFLAT / 128, BB, SS);
    dim3 gagg(TT, BB, SS);
    dim3 gmlp(NN, BB);

    adjbit_kernel<<<BB * SS, 256>>>(support);

    wh_kernel<<<gwh, 256>>>(x, W1, a1, 0);
    agg_kernel<<<gagg, 448>>>(0);

    wh_kernel<<<gwh, 256>>>(x, WK, aK, 1);
    agg_kernel<<<gagg, 448>>>(1);

    mlp_kernel<<<gmlp, 192>>>(x, mw, mb, out);
}

// round 16
// speedup vs baseline: 1.1215x; 1.1215x over previous
#include <cuda_runtime.h>
#include <cuda_bf16.h>

#define BB 16
#define FF 32
#define CC 32
#define NN 200
#define TT 48
#define SS 3
#define MC 16               // m-chunk in agg (2 k-steps of 8)
#define NCH 13              // 12 full chunks + 1 partial (8)
#define NP 224              // padded N (14 x 16-row mma bands)
#define WS 20               // wsm row stride (conflict-free)
#define WHS 40              // whs row stride (B-frag conflict-free)
#define NTFLAT (NN * TT)    // 9600

// ---- tf32 helpers ----
__device__ __forceinline__ unsigned tf32r(float f) {
    unsigned u; asm("cvt.rna.tf32.f32 %0, %1;" : "=r"(u) : "f"(f)); return u;
}
__device__ __forceinline__ void mma_tf32(float* d,
    unsigned a0, unsigned a1, unsigned a2, unsigned a3,
    unsigned b0, unsigned b1)
{
    asm("mma.sync.aligned.m16n8k8.row.col.f32.tf32.tf32.f32 "
        "{%0,%1,%2,%3}, {%4,%5,%6,%7}, {%8,%9}, {%0,%1,%2,%3};"
        : "+f"(d[0]), "+f"(d[1]), "+f"(d[2]), "+f"(d[3])
        : "r"(a0), "r"(a1), "r"(a2), "r"(a3), "r"(b0), "r"(b1));
}

// ---- cp.async helpers ----
__device__ __forceinline__ unsigned smem_u32(const void* p) {
    return (unsigned)__cvta_generic_to_shared(p);
}
#define CPA16(d, s) asm volatile("cp.async.cg.shared.global [%0], [%1], 16;" :: "r"(d), "l"(s))
#define CPC()       asm volatile("cp.async.commit_group;")
#define CPW0()      asm volatile("cp.async.wait_group 0;" ::: "memory")

// Scratch (device globals)
__device__ float g_wh[SS][BB][NTFLAT * CC];       // tf32-rounded Wh, [(n,t)][c]
__device__ float g_f1t[SS][BB][TT * NP];          // [t][n]
__device__ float g_f2t[SS][BB][TT * NP];          // [t][n]
__device__ unsigned g_adjb[BB * SS][NCH][NP];     // 16-bit masks per chunk
__device__ float g_y[6][BB][NTFLAT * CC];         // slot = 2*s + hop (tf32-rounded)
__device__ float g_mwt[224 * 64];                 // mlp weight, [c][o], tf32-rounded

// ---------------------------------------------------------------------------
// Adjacency bit-pack (16 bits per chunk word). grid 48, 256 threads.
// ---------------------------------------------------------------------------
__global__ void adjbit_kernel(const int* __restrict__ support)
{
    const int bs = blockIdx.x;
    const int warp = threadIdx.x >> 5, lane = threadIdx.x & 31;
    const int* adj = support + (size_t)bs * NN * NN;
    for (int pid = warp; pid < NN * NCH; pid += 8) {
        int n = pid / NCH, wi = pid % NCH;
        int mm = wi * MC + lane;
        int v = (lane < MC && mm < NN) ? (adj[n * NN + mm] > 0) : 0;
        unsigned word = __ballot_sync(0xffffffffu, v);
        if (lane == 0) g_adjb[bs][wi][n] = word;
    }
    if (threadIdx.x < NP - NN) {
        for (int wi = 0; wi < NCH; wi++) g_adjb[bs][wi][NN + threadIdx.x] = 0u;
    }
}

// ---------------------------------------------------------------------------
// mlp weight prep: transpose + tf32 round. grid 56, 256 threads.
// ---------------------------------------------------------------------------
__global__ void mwt_kernel(const float* __restrict__ mw)
{
    int idx = blockIdx.x * 256 + threadIdx.x;   // c*64+o
    if (idx < 224 * 64) {
        int c = idx >> 6, o = idx & 63;
        g_mwt[idx] = __uint_as_float(tf32r(mw[o * 224 + c]));
    }
}

// ---------------------------------------------------------------------------
// Wh + f1/f2 (t-major f-outputs; Wh stored pre-rounded to tf32).
// grid (75, BB, SS), 256 threads.
// ---------------------------------------------------------------------------
__global__ __launch_bounds__(256) void wh_kernel(
    const float* __restrict__ xin,
    const float* __restrict__ Wb,
    const float* __restrict__ ab,
    int layout)
{
    const int b = blockIdx.y, s = blockIdx.z;
    const int base = blockIdx.x * 128;
    const int tid = threadIdx.x;

    __shared__ float xs[128 * 33];
    __shared__ float Ws[FF * CC];
    __shared__ float as_[2 * CC];

    if (layout == 0) {
        const float* src = xin + (size_t)b * FF * NTFLAT + base;
        #pragma unroll
        for (int k = 0; k < 4; k++) {
            int idx4 = tid + 256 * k;
            int f = idx4 >> 5, r4 = (idx4 & 31) * 4;
            float4 v = *(const float4*)(src + (size_t)f * NTFLAT + r4);
            xs[(r4 + 0) * 33 + f] = v.x;
            xs[(r4 + 1) * 33 + f] = v.y;
            xs[(r4 + 2) * 33 + f] = v.z;
            xs[(r4 + 3) * 33 + f] = v.w;
        }
    } else {
        const float* src = &g_y[2 * s][b][(size_t)base * CC];
        #pragma unroll
        for (int k = 0; k < 4; k++) {
            int idx4 = tid + 256 * k;
            int row = idx4 >> 3, q = (idx4 & 7) * 4;
            float4 v = *(const float4*)(src + idx4 * 4);
            xs[row * 33 + q + 0] = v.x;
            xs[row * 33 + q + 1] = v.y;
            xs[row * 33 + q + 2] = v.z;
            xs[row * 33 + q + 3] = v.w;
        }
    }
    {
        const float* W = Wb + (s * BB + b) * (FF * CC);
        if (tid < 256) ((float4*)Ws)[tid] = ((const float4*)W)[tid];
        if (tid < 2 * CC) as_[tid] = ab[(s * BB + b) * (2 * CC) + tid];
    }
    __syncthreads();

    const int cg = tid & 15, rg = tid >> 4;
    const int r0 = rg * 8;
    float acc[8][2];
    #pragma unroll
    for (int i = 0; i < 8; i++) { acc[i][0] = 0.f; acc[i][1] = 0.f; }

    #pragma unroll 8
    for (int f = 0; f < FF; f++) {
        float2 wv = *(const float2*)&Ws[f * CC + 2 * cg];
        #pragma unroll
        for (int i = 0; i < 8; i++) {
            float xv = xs[(r0 + i) * 33 + f];
            acc[i][0] += xv * wv.x;
            acc[i][1] += xv * wv.y;
        }
    }

    float* hp = &g_wh[s][b][0];
    #pragma unroll
    for (int i = 0; i < 8; i++) {
        unsigned h0 = tf32r(acc[i][0]);
        unsigned h1 = tf32r(acc[i][1]);
        size_t off = (size_t)(base + r0 + i) * CC + 2 * cg;
        *(float2*)&hp[off] = make_float2(__uint_as_float(h0), __uint_as_float(h1));
    }

    float a1l = as_[2 * cg], a1h = as_[2 * cg + 1];
    float a2l = as_[CC + 2 * cg], a2h = as_[CC + 2 * cg + 1];
    #pragma unroll
    for (int i = 0; i < 8; i++) {
        float p1 = acc[i][0] * a1l + acc[i][1] * a1h;
        float p2 = acc[i][0] * a2l + acc[i][1] * a2h;
        #pragma unroll
        for (int off = 8; off >= 1; off >>= 1) {
            p1 += __shfl_xor_sync(0xffffffffu, p1, off);
            p2 += __shfl_xor_sync(0xffffffffu, p2, off);
        }
        if (cg == 0) {
            int row = base + r0 + i;
            int n = row / TT, t = row % TT;
            g_f1t[s][b][t * NP + n] = p1;
            g_f2t[s][b][t * NP + n] = p2;
        }
    }
}

// ---------------------------------------------------------------------------
// Attention-aggregation, 1x tf32 mma, fused single-barrier pipeline.
// grid (TT, BB, SS), block 448 (14 warps). Warp w owns n-rows [16w, 16w+16).
// ---------------------------------------------------------------------------
__global__ __launch_bounds__(448, 2) void agg_kernel(int hop)
{
    const int t = blockIdx.x, b = blockIdx.y, s = blockIdx.z;
    const int bs = b * SS + s;
    const int tid = threadIdx.x;
    const int lane = tid & 31, wid = tid >> 5;
    const int grp = lane >> 2, kq = lane & 3;

    __shared__ __align__(16) float whs[2][MC * WHS];     // [m][c] stride 40
    __shared__ __align__(16) float wsm[2][NP * WS];      // [n][m] stride 20
    __shared__ __align__(16) unsigned adjw[2][NP];
    __shared__ float f2all[NP];
    __shared__ float zsm[NP];

    const float* whbase = &g_wh[s][b][0];
    const float* f1tp = &g_f1t[s][b][t * NP];
    const float* f2tp = &g_f2t[s][b][t * NP];

    auto prefetch_whs = [&](int k) {
        const int bf = k & 1;
        if (tid < MC * 8) {
            int m = tid >> 3, q = tid & 7;
            int mrow = min(k * MC + m, NN - 1);
            CPA16(smem_u32(&whs[bf][m * WHS + q * 4]),
                  whbase + ((size_t)mrow * TT + t) * CC + q * 4);
        }
    };
    auto prefetch_adj = [&](int k) {
        const int bf = k & 1;
        if (tid < NP / 4)
            CPA16(smem_u32(&adjw[bf][tid * 4]), &g_adjb[bs][k][tid * 4]);
    };

    float f1v = 0.f, mhv = 0.f, z = 0.f;

    auto step1 = [&](int kk) {
        if (tid < NN) {
            const int bf = kk & 1;
            unsigned aw = adjw[bf][tid];
            const int mcn = (kk == NCH - 1) ? (NN - (NCH - 1) * MC) : MC;
            const int mb = kk * MC;
            #pragma unroll
            for (int q = 0; q < MC / 4; q++) {
                if (4 * q >= mcn) break;
                float4 wq;
                float* wp = &wq.x;
                #pragma unroll
                for (int j = 0; j < 4; j++) {
                    int m = 4 * q + j;
                    float sv = f1v + f2all[mb + m];
                    float e = fmaxf(sv, 0.2f * sv);
                    float w = ((aw >> m) & 1u) ? __expf(e - mhv) : 0.f;
                    float wr = __uint_as_float(tf32r(w));
                    wp[j] = wr;
                    z += wr;
                }
                *(float4*)&wsm[bf][tid * WS + 4 * q] = wq;
            }
        }
    };

    prefetch_whs(0);
    prefetch_adj(0);
    prefetch_adj(1);
    CPC();

    if (tid < NP) f2all[tid] = (tid < NN) ? f2tp[tid] : -1e30f;
    for (int i = tid; i < (NP - NN) * WS; i += 448) {
        int n = NN + i / WS, m = i % WS;
        wsm[0][n * WS + m] = 0.f;
        wsm[1][n * WS + m] = 0.f;
    }

    CPW0();
    __syncthreads();

    float fms;
    {
        float m = -1e30f;
        #pragma unroll
        for (int i = 0; i < 7; i++) m = fmaxf(m, f2all[lane + 32 * i]);
        #pragma unroll
        for (int off = 16; off >= 1; off >>= 1)
            m = fmaxf(m, __shfl_xor_sync(0xffffffffu, m, off));
        fms = m;
    }
    if (tid < NN) {
        f1v = f1tp[tid];
        float sv = f1v + fms;
        mhv = fmaxf(sv, 0.2f * sv);
    }

    step1(0);
    __syncthreads();

    float d[4][4];
    #pragma unroll
    for (int j = 0; j < 4; j++)
        #pragma unroll
        for (int q = 0; q < 4; q++) d[j][q] = 0.f;

    const int r0 = 16 * wid + grp;

    for (int k = 0; k < NCH; k++) {
        const int bf = k & 1;
        if (k + 1 < NCH) prefetch_whs(k + 1);
        if (k + 2 < NCH) prefetch_adj(k + 2);
        CPC();

        if (k + 1 < NCH) step1(k + 1);

        const int mc = (k == NCH - 1) ? (NN - (NCH - 1) * MC) : MC;
        const int nks = mc >> 3;
        for (int ks = 0; ks < nks; ks++) {
            unsigned a0 = __float_as_uint(wsm[bf][r0 * WS + ks * 8 + kq]);
            unsigned a1 = __float_as_uint(wsm[bf][(r0 + 8) * WS + ks * 8 + kq]);
            unsigned a2 = __float_as_uint(wsm[bf][r0 * WS + ks * 8 + kq + 4]);
            unsigned a3 = __float_as_uint(wsm[bf][(r0 + 8) * WS + ks * 8 + kq + 4]);
            #pragma unroll
            for (int j = 0; j < 4; j++) {
                int c0 = 8 * j + grp;
                int mr = ks * 8 + kq;
                unsigned bh0 = __float_as_uint(whs[bf][mr * WHS + c0]);
                unsigned bh1 = __float_as_uint(whs[bf][(mr + 4) * WHS + c0]);
                mma_tf32(d[j], a0, a1, a2, a3, bh0, bh1);
            }
        }

        CPW0();
        __syncthreads();
    }

    if (tid < NN) zsm[tid] = z;
    __syncthreads();

    const int slot = 2 * s + hop;
    float* yp = &g_y[slot][b][0];
    #pragma unroll
    for (int half = 0; half < 2; half++) {
        int n = r0 + 8 * half;
        if (n < NN) {
            float zv = fmaxf(zsm[n], 1e-30f);
            #pragma unroll
            for (int j = 0; j < 4; j++) {
                float h0 = __fdividef(d[j][2 * half], zv);
                float h1 = __fdividef(d[j][2 * half + 1], zv);
                float y0, y1;
                if (hop == 0) {
                    y0 = (h0 > 0.f) ? h0 : (__expf(h0) - 1.f);
                    y1 = (h1 > 0.f) ? h1 : (__expf(h1) - 1.f);
                } else {
                    y0 = fmaxf(h0, 0.f);
                    y1 = fmaxf(h1, 0.f);
                }
                // store tf32-rounded (consumed by tf32 mma in mlp; wh hop2 fp32-safe)
                *(float2*)&yp[(size_t)(n * TT + t) * CC + 8 * j + 2 * kq] =
                    make_float2(__uint_as_float(tf32r(y0)), __uint_as_float(tf32r(y1)));
            }
        }
    }
}

// ---------------------------------------------------------------------------
// Final concat + 1x1 conv via tf32 mma. grid (NN, BB), block 192 (6 warps).
// Warp: band = wid>>1 (t-rows 16*band..+16), ohalf = wid&1 (o-cols 32*ohalf..+32).
// K = 224 in 7 chunks of 32.
// ---------------------------------------------------------------------------
__global__ __launch_bounds__(192) void mlp_kernel(
    const float* __restrict__ x,
    const float* __restrict__ mb,
    float* __restrict__ out)
{
    const int n = blockIdx.x, b = blockIdx.y;
    const int tid = threadIdx.x;
    const int lane = tid & 31, wid = tid >> 5;
    const int grp = lane >> 2, kq = lane & 3;

    __shared__ __align__(16) float hb[2][TT * 36];      // [t][c] stride 36
    __shared__ __align__(16) float wbt[2][32 * 72];     // [c][o] stride 72
    __shared__ float outb[TT * 65];                     // [t][o] stride 65

    auto prefetch = [&](int blk, int bf) {
        const float* src = &g_y[blk - 1][b][(size_t)n * TT * CC];
        for (int i = tid; i < 384; i += 192) {
            int row = i >> 3, q = i & 7;
            CPA16(smem_u32(&hb[bf][row * 36 + q * 4]), src + i * 4);
        }
        for (int i = tid; i < 512; i += 192) {
            int cr = i >> 4, q = i & 15;
            CPA16(smem_u32(&wbt[bf][cr * 72 + q * 4]),
                  &g_mwt[(blk * 32 + cr) * 64 + q * 4]);
        }
        CPC();
    };

    // blk 0: transpose-load x with tf32 rounding; wbt chunk 0 from g_mwt
    for (int idx = tid; idx < TT * 32; idx += 192) {
        int f = idx / TT, t = idx % TT;
        hb[0][t * 36 + f] = __uint_as_float(
            tf32r(x[((size_t)(b * FF + f) * NN + n) * TT + t]));
    }
    for (int i = tid; i < 512; i += 192) {
        int cr = i >> 4, q = i & 15;
        *(float4*)&wbt[0][cr * 72 + q * 4] = *(const float4*)&g_mwt[cr * 64 + q * 4];
    }
    prefetch(1, 1);
    __syncthreads();

    const int band = wid >> 1, ohalf = wid & 1;
    const int tr0 = 16 * band + grp;

    float d[4][4];
    #pragma unroll
    for (int j = 0; j < 4; j++)
        #pragma unroll
        for (int q = 0; q < 4; q++) d[j][q] = 0.f;

    for (int blk = 0; blk < 7; blk++) {
        const int bf = blk & 1;
        #pragma unroll
        for (int ks = 0; ks < 4; ks++) {
            int kb = ks * 8 + kq;
            unsigned a0 = __float_as_uint(hb[bf][tr0 * 36 + kb]);
            unsigned a1 = __float_as_uint(hb[bf][(tr0 + 8) * 36 + kb]);
            unsigned a2 = __float_as_uint(hb[bf][tr0 * 36 + kb + 4]);
            unsigned a3 = __float_as_uint(hb[bf][(tr0 + 8) * 36 + kb + 4]);
            #pragma unroll
            for (int j = 0; j < 4; j++) {
                int o0 = 32 * ohalf + 8 * j + grp;
                unsigned b0 = __float_as_uint(wbt[bf][kb * 72 + o0]);
                unsigned b1 = __float_as_uint(wbt[bf][(kb + 4) * 72 + o0]);
                mma_tf32(d[j], a0, a1, a2, a3, b0, b1);
            }
        }
        if (blk + 1 < 7) {
            CPW0();
            __syncthreads();
            if (blk + 2 < 7) prefetch(blk + 2, bf);
        }
    }

    // stage D to smem [t][o]
    #pragma unroll
    for (int half = 0; half < 2; half++) {
        int t = tr0 + 8 * half;
        #pragma unroll
        for (int j = 0; j < 4; j++) {
            int o = 32 * ohalf + 8 * j + 2 * kq;
            outb[t * 65 + o]     = d[j][2 * half];
            outb[t * 65 + o + 1] = d[j][2 * half + 1];
        }
    }
    __syncthreads();

    // coalesced output: thread covers (o, t4)
    for (int i = tid; i < 64 * 12; i += 192) {
        int o = i / 12, t4 = (i % 12) * 4;
        float bias = mb[o];
        float4 r;
        r.x = outb[(t4 + 0) * 65 + o] + bias;
        r.y = outb[(t4 + 1) * 65 + o] + bias;
        r.z = outb[(t4 + 2) * 65 + o] + bias;
        r.w = outb[(t4 + 3) * 65 + o] + bias;
        *(float4*)&out[((size_t)(b * 64 + o) * NN + n) * TT + t4] = r;
    }
}

// ---------------------------------------------------------------------------
extern "C" void kernel_launch(void* const* d_in, const int* in_sizes, int n_in,
                              void* d_out, int out_size)
{
    const float* x       = (const float*)d_in[0];
    const int*   support = (const int*)  d_in[1];
    const float* W1      = (const float*)d_in[2];
    const float* a1      = (const float*)d_in[3];
    const float* WK      = (const float*)d_in[4];
    const float* aK      = (const float*)d_in[5];
    const float* mw      = (const float*)d_in[6];
    const float* mb      = (const float*)d_in[7];
    float* out = (float*)d_out;

    dim3 gwh(NTFLAT / 128, BB, SS);
    dim3 gagg(TT, BB, SS);
    dim3 gmlp(NN, BB);

    adjbit_kernel<<<BB * SS, 256>>>(support);
    mwt_kernel<<<56, 256>>>(mw);

    wh_kernel<<<gwh, 256>>>(x, W1, a1, 0);
    agg_kernel<<<gagg, 448>>>(0);

    wh_kernel<<<gwh, 256>>>(x, WK, aK, 1);
    agg_kernel<<<gagg, 448>>>(1);

    mlp_kernel<<<gmlp, 192>>>(x, mb, out);
}

// round 17
// speedup vs baseline: 1.3248x; 1.1813x over previous
#include <cuda_runtime.h>
#include <cuda_bf16.h>

#define BB 16
#define FF 32
#define CC 32
#define NN 200
#define TT 48
#define SS 3
#define MC 16               // m-chunk in agg (2 k-steps of 8)
#define NCH 13              // 12 full chunks + 1 partial (8)
#define NP 224              // padded N (14 x 16-row mma bands)
#define WS 20               // wsm row stride (conflict-free)
#define WHS 40              // whs row stride (B-frag conflict-free)
#define NTFLAT (NN * TT)    // 9600

// ---- tf32 helpers ----
__device__ __forceinline__ unsigned tf32r(float f) {
    unsigned u; asm("cvt.rna.tf32.f32 %0, %1;" : "=r"(u) : "f"(f)); return u;
}
__device__ __forceinline__ void mma_tf32(float* d,
    unsigned a0, unsigned a1, unsigned a2, unsigned a3,
    unsigned b0, unsigned b1)
{
    asm("mma.sync.aligned.m16n8k8.row.col.f32.tf32.tf32.f32 "
        "{%0,%1,%2,%3}, {%4,%5,%6,%7}, {%8,%9}, {%0,%1,%2,%3};"
        : "+f"(d[0]), "+f"(d[1]), "+f"(d[2]), "+f"(d[3])
        : "r"(a0), "r"(a1), "r"(a2), "r"(a3), "r"(b0), "r"(b1));
}

// ---- cp.async helpers ----
__device__ __forceinline__ unsigned smem_u32(const void* p) {
    return (unsigned)__cvta_generic_to_shared(p);
}
#define CPA16(d, s) asm volatile("cp.async.cg.shared.global [%0], [%1], 16;" :: "r"(d), "l"(s))
#define CPC()       asm volatile("cp.async.commit_group;")
#define CPW0()      asm volatile("cp.async.wait_group 0;" ::: "memory")

// Scratch (device globals)
__device__ float g_wh[SS][BB][NTFLAT * CC];       // tf32-rounded Wh, [(n,t)][c]
__device__ float g_f1t[SS][BB][TT * NP];          // [t][n]
__device__ float g_f2t[SS][BB][TT * NP];          // [t][n]
__device__ unsigned g_adjb[BB * SS][NCH][NP];     // 16-bit masks per chunk
__device__ float g_y[6][BB][NTFLAT * CC];         // slot = 2*s + hop (tf32-rounded)
__device__ float g_mwt[224 * 64];                 // mlp weight, [c][o], tf32-rounded

// ---------------------------------------------------------------------------
// Adjacency bit-pack (16 bits per chunk word). grid 48, 256 threads.
// ---------------------------------------------------------------------------
__global__ void adjbit_kernel(const int* __restrict__ support)
{
    const int bs = blockIdx.x;
    const int warp = threadIdx.x >> 5, lane = threadIdx.x & 31;
    const int* adj = support + (size_t)bs * NN * NN;
    for (int pid = warp; pid < NN * NCH; pid += 8) {
        int n = pid / NCH, wi = pid % NCH;
        int mm = wi * MC + lane;
        int v = (lane < MC && mm < NN) ? (adj[n * NN + mm] > 0) : 0;
        unsigned word = __ballot_sync(0xffffffffu, v);
        if (lane == 0) g_adjb[bs][wi][n] = word;
    }
    if (threadIdx.x < NP - NN) {
        for (int wi = 0; wi < NCH; wi++) g_adjb[bs][wi][NN + threadIdx.x] = 0u;
    }
}

// ---------------------------------------------------------------------------
// mlp weight prep: transpose + tf32 round. grid 56, 256 threads.
// ---------------------------------------------------------------------------
__global__ void mwt_kernel(const float* __restrict__ mw)
{
    int idx = blockIdx.x * 256 + threadIdx.x;   // c*64+o
    if (idx < 224 * 64) {
        int c = idx >> 6, o = idx & 63;
        g_mwt[idx] = __uint_as_float(tf32r(mw[o * 224 + c]));
    }
}

// ---------------------------------------------------------------------------
// Wh + f1/f2 (t-major f-outputs; Wh stored pre-rounded to tf32).
// grid (75, BB, SS), 256 threads.
// ---------------------------------------------------------------------------
__global__ __launch_bounds__(256) void wh_kernel(
    const float* __restrict__ xin,
    const float* __restrict__ Wb,
    const float* __restrict__ ab,
    int layout)
{
    const int b = blockIdx.y, s = blockIdx.z;
    const int base = blockIdx.x * 128;
    const int tid = threadIdx.x;

    __shared__ float xs[128 * 33];
    __shared__ float Ws[FF * CC];
    __shared__ float as_[2 * CC];

    if (layout == 0) {
        const float* src = xin + (size_t)b * FF * NTFLAT + base;
        #pragma unroll
        for (int k = 0; k < 4; k++) {
            int idx4 = tid + 256 * k;
            int f = idx4 >> 5, r4 = (idx4 & 31) * 4;
            float4 v = *(const float4*)(src + (size_t)f * NTFLAT + r4);
            xs[(r4 + 0) * 33 + f] = v.x;
            xs[(r4 + 1) * 33 + f] = v.y;
            xs[(r4 + 2) * 33 + f] = v.z;
            xs[(r4 + 3) * 33 + f] = v.w;
        }
    } else {
        const float* src = &g_y[2 * s][b][(size_t)base * CC];
        #pragma unroll
        for (int k = 0; k < 4; k++) {
            int idx4 = tid + 256 * k;
            int row = idx4 >> 3, q = (idx4 & 7) * 4;
            float4 v = *(const float4*)(src + idx4 * 4);
            xs[row * 33 + q + 0] = v.x;
            xs[row * 33 + q + 1] = v.y;
            xs[row * 33 + q + 2] = v.z;
            xs[row * 33 + q + 3] = v.w;
        }
    }
    {
        const float* W = Wb + (s * BB + b) * (FF * CC);
        if (tid < 256) ((float4*)Ws)[tid] = ((const float4*)W)[tid];
        if (tid < 2 * CC) as_[tid] = ab[(s * BB + b) * (2 * CC) + tid];
    }
    __syncthreads();

    const int cg = tid & 15, rg = tid >> 4;
    const int r0 = rg * 8;
    float acc[8][2];
    #pragma unroll
    for (int i = 0; i < 8; i++) { acc[i][0] = 0.f; acc[i][1] = 0.f; }

    #pragma unroll 8
    for (int f = 0; f < FF; f++) {
        float2 wv = *(const float2*)&Ws[f * CC + 2 * cg];
        #pragma unroll
        for (int i = 0; i < 8; i++) {
            float xv = xs[(r0 + i) * 33 + f];
            acc[i][0] += xv * wv.x;
            acc[i][1] += xv * wv.y;
        }
    }

    float* hp = &g_wh[s][b][0];
    #pragma unroll
    for (int i = 0; i < 8; i++) {
        unsigned h0 = tf32r(acc[i][0]);
        unsigned h1 = tf32r(acc[i][1]);
        size_t off = (size_t)(base + r0 + i) * CC + 2 * cg;
        *(float2*)&hp[off] = make_float2(__uint_as_float(h0), __uint_as_float(h1));
    }

    float a1l = as_[2 * cg], a1h = as_[2 * cg + 1];
    float a2l = as_[CC + 2 * cg], a2h = as_[CC + 2 * cg + 1];
    #pragma unroll
    for (int i = 0; i < 8; i++) {
        float p1 = acc[i][0] * a1l + acc[i][1] * a1h;
        float p2 = acc[i][0] * a2l + acc[i][1] * a2h;
        #pragma unroll
        for (int off = 8; off >= 1; off >>= 1) {
            p1 += __shfl_xor_sync(0xffffffffu, p1, off);
            p2 += __shfl_xor_sync(0xffffffffu, p2, off);
        }
        if (cg == 0) {
            int row = base + r0 + i;
            int n = row / TT, t = row % TT;
            g_f1t[s][b][t * NP + n] = p1;
            g_f2t[s][b][t * NP + n] = p2;
        }
    }
}

// ---------------------------------------------------------------------------
// Attention-aggregation, 1x tf32 mma, fused single-barrier pipeline.
// step1 spread over ALL 448 threads: task = n*4 + m-quad; thread owns tasks
// tid and tid+448 (same quad qq = tid&3, n's tid>>2 and +112).
// grid (TT, BB, SS), block 448 (14 warps). Warp w owns n-rows [16w, 16w+16).
// ---------------------------------------------------------------------------
__global__ __launch_bounds__(448, 2) void agg_kernel(int hop)
{
    const int t = blockIdx.x, b = blockIdx.y, s = blockIdx.z;
    const int bs = b * SS + s;
    const int tid = threadIdx.x;
    const int lane = tid & 31, wid = tid >> 5;
    const int grp = lane >> 2, kq = lane & 3;

    __shared__ __align__(16) float whs[2][MC * WHS];     // [m][c] stride 40
    __shared__ __align__(16) float wsm[2][NP * WS];      // [n][m] stride 20
    __shared__ __align__(16) unsigned adjw[2][NP];
    __shared__ float f2all[NP];
    __shared__ float zsm[NP];

    const float* whbase = &g_wh[s][b][0];
    const float* f1tp = &g_f1t[s][b][t * NP];
    const float* f2tp = &g_f2t[s][b][t * NP];

    auto prefetch_whs = [&](int k) {
        const int bf = k & 1;
        if (tid < MC * 8) {
            int m = tid >> 3, q = tid & 7;
            int mrow = min(k * MC + m, NN - 1);
            CPA16(smem_u32(&whs[bf][m * WHS + q * 4]),
                  whbase + ((size_t)mrow * TT + t) * CC + q * 4);
        }
    };
    auto prefetch_adj = [&](int k) {
        const int bf = k & 1;
        if (tid < NP / 4)
            CPA16(smem_u32(&adjw[bf][tid * 4]), &g_adjb[bs][k][tid * 4]);
    };

    // step1 task state (fixed n per thread across all chunks)
    const int qq = tid & 3;              // m-quad: m = qq*4 + j
    const int n0 = tid >> 2;             // task 0 row (always < 200 for tid < 448? n0 < 112)
    const int n1 = n0 + 112;             // task 1 row (valid if < 200)
    const bool t1ok = (n1 < NN);         // tid < 352
    float f1v0 = 0.f, mhv0 = 0.f, f1v1 = 0.f, mhv1 = 0.f;
    float z0 = 0.f, z1 = 0.f;

    auto step1 = [&](int kk) {
        const int bf = kk & 1;
        const int mb = kk * MC;
        const int mcn = (kk == NCH - 1) ? (NN - (NCH - 1) * MC) : MC;
        if (4 * qq < mcn) {
            float f2q[4];
            #pragma unroll
            for (int j = 0; j < 4; j++) f2q[j] = f2all[mb + 4 * qq + j];
            {
                unsigned aw = adjw[bf][n0];
                float4 wq;
                float* wp = &wq.x;
                #pragma unroll
                for (int j = 0; j < 4; j++) {
                    int m = 4 * qq + j;
                    float sv = f1v0 + f2q[j];
                    float e = fmaxf(sv, 0.2f * sv);
                    float w = ((aw >> m) & 1u) ? __expf(e - mhv0) : 0.f;
                    float wr = __uint_as_float(tf32r(w));
                    wp[j] = wr;
                    z0 += wr;
                }
                *(float4*)&wsm[bf][n0 * WS + 4 * qq] = wq;
            }
            if (t1ok) {
                unsigned aw = adjw[bf][n1];
                float4 wq;
                float* wp = &wq.x;
                #pragma unroll
                for (int j = 0; j < 4; j++) {
                    int m = 4 * qq + j;
                    float sv = f1v1 + f2q[j];
                    float e = fmaxf(sv, 0.2f * sv);
                    float w = ((aw >> m) & 1u) ? __expf(e - mhv1) : 0.f;
                    float wr = __uint_as_float(tf32r(w));
                    wp[j] = wr;
                    z1 += wr;
                }
                *(float4*)&wsm[bf][n1 * WS + 4 * qq] = wq;
            }
        }
    };

    prefetch_whs(0);
    prefetch_adj(0);
    prefetch_adj(1);
    CPC();

    if (tid < NP) f2all[tid] = (tid < NN) ? f2tp[tid] : -1e30f;
    for (int i = tid; i < (NP - NN) * WS; i += 448) {
        int n = NN + i / WS, m = i % WS;
        wsm[0][n * WS + m] = 0.f;
        wsm[1][n * WS + m] = 0.f;
    }

    CPW0();
    __syncthreads();

    float fms;
    {
        float m = -1e30f;
        #pragma unroll
        for (int i = 0; i < 7; i++) m = fmaxf(m, f2all[lane + 32 * i]);
        #pragma unroll
        for (int off = 16; off >= 1; off >>= 1)
            m = fmaxf(m, __shfl_xor_sync(0xffffffffu, m, off));
        fms = m;
    }
    {
        f1v0 = f1tp[n0];
        float sv = f1v0 + fms;
        mhv0 = fmaxf(sv, 0.2f * sv);
        if (t1ok) {
            f1v1 = f1tp[n1];
            float sv1 = f1v1 + fms;
            mhv1 = fmaxf(sv1, 0.2f * sv1);
        }
    }

    step1(0);
    __syncthreads();

    float d[4][4];
    #pragma unroll
    for (int j = 0; j < 4; j++)
        #pragma unroll
        for (int q = 0; q < 4; q++) d[j][q] = 0.f;

    const int r0 = 16 * wid + grp;

    for (int k = 0; k < NCH; k++) {
        const int bf = k & 1;
        if (k + 1 < NCH) prefetch_whs(k + 1);
        if (k + 2 < NCH) prefetch_adj(k + 2);
        CPC();

        if (k + 1 < NCH) step1(k + 1);

        const int mc = (k == NCH - 1) ? (NN - (NCH - 1) * MC) : MC;
        const int nks = mc >> 3;
        for (int ks = 0; ks < nks; ks++) {
            unsigned a0 = __float_as_uint(wsm[bf][r0 * WS + ks * 8 + kq]);
            unsigned a1 = __float_as_uint(wsm[bf][(r0 + 8) * WS + ks * 8 + kq]);
            unsigned a2 = __float_as_uint(wsm[bf][r0 * WS + ks * 8 + kq + 4]);
            unsigned a3 = __float_as_uint(wsm[bf][(r0 + 8) * WS + ks * 8 + kq + 4]);
            #pragma unroll
            for (int j = 0; j < 4; j++) {
                int c0 = 8 * j + grp;
                int mr = ks * 8 + kq;
                unsigned bh0 = __float_as_uint(whs[bf][mr * WHS + c0]);
                unsigned bh1 = __float_as_uint(whs[bf][(mr + 4) * WHS + c0]);
                mma_tf32(d[j], a0, a1, a2, a3, bh0, bh1);
            }
        }

        CPW0();
        __syncthreads();
    }

    // Z reduction: partials -> zpart (aliases dead wsm[0]) -> zsm[n]
    {
        float* zpart = &wsm[0][0];       // 800 floats, free after final barrier
        zpart[tid] = z0;
        if (t1ok) zpart[tid + 448] = z1;
        __syncthreads();
        if (tid < NN)
            zsm[tid] = (zpart[4 * tid] + zpart[4 * tid + 1])
                     + (zpart[4 * tid + 2] + zpart[4 * tid + 3]);
        __syncthreads();
    }

    const int slot = 2 * s + hop;
    float* yp = &g_y[slot][b][0];
    #pragma unroll
    for (int half = 0; half < 2; half++) {
        int n = r0 + 8 * half;
        if (n < NN) {
            float zv = fmaxf(zsm[n], 1e-30f);
            #pragma unroll
            for (int j = 0; j < 4; j++) {
                float h0 = __fdividef(d[j][2 * half], zv);
                float h1 = __fdividef(d[j][2 * half + 1], zv);
                float y0, y1;
                if (hop == 0) {
                    y0 = (h0 > 0.f) ? h0 : (__expf(h0) - 1.f);
                    y1 = (h1 > 0.f) ? h1 : (__expf(h1) - 1.f);
                } else {
                    y0 = fmaxf(h0, 0.f);
                    y1 = fmaxf(h1, 0.f);
                }
                *(float2*)&yp[(size_t)(n * TT + t) * CC + 8 * j + 2 * kq] =
                    make_float2(__uint_as_float(tf32r(y0)), __uint_as_float(tf32r(y1)));
            }
        }
    }
}

// ---------------------------------------------------------------------------
// Final concat + 1x1 conv via tf32 mma. grid (NN, BB), block 192 (6 warps).
// ---------------------------------------------------------------------------
__global__ __launch_bounds__(192) void mlp_kernel(
    const float* __restrict__ x,
    const float* __restrict__ mb,
    float* __restrict__ out)
{
    const int n = blockIdx.x, b = blockIdx.y;
    const int tid = threadIdx.x;
    const int lane = tid & 31, wid = tid >> 5;
    const int grp = lane >> 2, kq = lane & 3;

    __shared__ __align__(16) float hb[2][TT * 36];      // [t][c] stride 36
    __shared__ __align__(16) float wbt[2][32 * 72];     // [c][o] stride 72
    __shared__ float outb[TT * 65];                     // [t][o] stride 65

    auto prefetch = [&](int blk, int bf) {
        const float* src = &g_y[blk - 1][b][(size_t)n * TT * CC];
        for (int i = tid; i < 384; i += 192) {
            int row = i >> 3, q = i & 7;
            CPA16(smem_u32(&hb[bf][row * 36 + q * 4]), src + i * 4);
        }
        for (int i = tid; i < 512; i += 192) {
            int cr = i >> 4, q = i & 15;
            CPA16(smem_u32(&wbt[bf][cr * 72 + q * 4]),
                  &g_mwt[(blk * 32 + cr) * 64 + q * 4]);
        }
        CPC();
    };

    for (int idx = tid; idx < TT * 32; idx += 192) {
        int f = idx / TT, t = idx % TT;
        hb[0][t * 36 + f] = __uint_as_float(
            tf32r(x[((size_t)(b * FF + f) * NN + n) * TT + t]));
    }
    for (int i = tid; i < 512; i += 192) {
        int cr = i >> 4, q = i & 15;
        *(float4*)&wbt[0][cr * 72 + q * 4] = *(const float4*)&g_mwt[cr * 64 + q * 4];
    }
    prefetch(1, 1);
    __syncthreads();

    const int band = wid >> 1, ohalf = wid & 1;
    const int tr0 = 16 * band + grp;

    float d[4][4];
    #pragma unroll
    for (int j = 0; j < 4; j++)
        #pragma unroll
        for (int q = 0; q < 4; q++) d[j][q] = 0.f;

    for (int blk = 0; blk < 7; blk++) {
        const int bf = blk & 1;
        #pragma unroll
        for (int ks = 0; ks < 4; ks++) {
            int kb = ks * 8 + kq;
            unsigned a0 = __float_as_uint(hb[bf][tr0 * 36 + kb]);
            unsigned a1 = __float_as_uint(hb[bf][(tr0 + 8) * 36 + kb]);
            unsigned a2 = __float_as_uint(hb[bf][tr0 * 36 + kb + 4]);
            unsigned a3 = __float_as_uint(hb[bf][(tr0 + 8) * 36 + kb + 4]);
            #pragma unroll
            for (int j = 0; j < 4; j++) {
                int o0 = 32 * ohalf + 8 * j + grp;
                unsigned b0 = __float_as_uint(wbt[bf][kb * 72 + o0]);
                unsigned b1 = __float_as_uint(wbt[bf][(kb + 4) * 72 + o0]);
                mma_tf32(d[j], a0, a1, a2, a3, b0, b1);
            }
        }
        if (blk + 1 < 7) {
            CPW0();
            __syncthreads();
            if (blk + 2 < 7) prefetch(blk + 2, bf);
        }
    }

    #pragma unroll
    for (int half = 0; half < 2; half++) {
        int t = tr0 + 8 * half;
        #pragma unroll
        for (int j = 0; j < 4; j++) {
            int o = 32 * ohalf + 8 * j + 2 * kq;
            outb[t * 65 + o]     = d[j][2 * half];
            outb[t * 65 + o + 1] = d[j][2 * half + 1];
        }
    }
    __syncthreads();

    for (int i = tid; i < 64 * 12; i += 192) {
        int o = i / 12, t4 = (i % 12) * 4;
        float bias = mb[o];
        float4 r;
        r.x = outb[(t4 + 0) * 65 + o] + bias;
        r.y = outb[(t4 + 1) * 65 + o] + bias;
        r.z = outb[(t4 + 2) * 65 + o] + bias;
        r.w = outb[(t4 + 3) * 65 + o] + bias;
        *(float4*)&out[((size_t)(b * 64 + o) * NN + n) * TT + t4] = r;
    }
}

// ---------------------------------------------------------------------------
extern "C" void kernel_launch(void* const* d_in, const int* in_sizes, int n_in,
                              void* d_out, int out_size)
{
    const float* x       = (const float*)d_in[0];
    const int*   support = (const int*)  d_in[1];
    const float* W1      = (const float*)d_in[2];
    const float* a1      = (const float*)d_in[3];
    const float* WK      = (const float*)d_in[4];
    const float* aK      = (const float*)d_in[5];
    const float* mw      = (const float*)d_in[6];
    const float* mb      = (const float*)d_in[7];
    float* out = (float*)d_out;

    dim3 gwh(NTFLAT / 128, BB, SS);
    dim3 gagg(TT, BB, SS);
    dim3 gmlp(NN, BB);

    adjbit_kernel<<<BB * SS, 256>>>(support);
    mwt_kernel<<<56, 256>>>(mw);

    wh_kernel<<<gwh, 256>>>(x, W1, a1, 0);
    agg_kernel<<<gagg, 448>>>(0);

    wh_kernel<<<gwh, 256>>>(x, WK, aK, 1);
    agg_kernel<<<gagg, 448>>>(1);

    mlp_kernel<<<gmlp, 192>>>(x, mb, out);
}